// round 1
// baseline (speedup 1.0000x reference)
#include <cuda_runtime.h>
#include <cstddef>

// DynMoleRouterLoss: L=32 layers, B*S=32768 tokens, E=16 experts.
// Mapping: warp <-> token t, lane <-> layer l, row = l*BS + t.
// attention weight w = attn[t] is warp-uniform => sort/top-p/accumulate
// path is skipped without divergence for w==0 warps (~half).

namespace {
constexpr int   L_     = 32;
constexpr int   BS_    = 8 * 4096;      // 32768 tokens
constexpr int   E_     = 16;
constexpr float TOPP_  = 0.8f;
constexpr float EPSF_  = 1e-5f;
constexpr float BCT_   = 2.0f;          // broadcast entropy threshold
constexpr float L2E_   = 1.4426950408889634f;
constexpr float DYN_   = 0.001f;
constexpr float AUX_   = 0.001f;
constexpr float NROWSF = 1048576.0f;    // L*BS
}

// global accumulators: [0..15]=A (token counts per rank), [16..31]=P (prob sums per rank), [32]=entropy sum
__device__ float g_acc[33];

__global__ void dynmole_init() {
    if (threadIdx.x < 33) g_acc[threadIdx.x] = 0.0f;
}

__device__ __forceinline__ float ex2f(float x) {
    float y;
    asm("ex2.approx.ftz.f32 %0, %1;" : "=f"(y) : "f"(x));
    return y;
}

// compare-exchange for DESCENDING order: v[i] >= v[j] afterwards
#define CE(i, j) { float _a = v[i], _b = v[j]; v[i] = fmaxf(_a, _b); v[j] = fminf(_a, _b); }

__global__ __launch_bounds__(256, 2) void dynmole_main(
        const float* __restrict__ logits, const int* __restrict__ attn) {
    const int lane = threadIdx.x & 31;
    const int wg   = (blockIdx.x * blockDim.x + threadIdx.x) >> 5;
    const int nw   = (gridDim.x * blockDim.x) >> 5;

    float A[16], P[16];
#pragma unroll
    for (int r = 0; r < 16; r++) { A[r] = 0.0f; P[r] = 0.0f; }
    float entS = 0.0f;

    for (int t = wg; t < BS_; t += nw) {
        const int w = __ldg(attn + t);                // warp-uniform
        const float4* rowp = reinterpret_cast<const float4*>(
            logits + ((size_t)lane * BS_ + (size_t)t) * E_);
        float4 q0 = __ldg(rowp + 0);
        float4 q1 = __ldg(rowp + 1);
        float4 q2 = __ldg(rowp + 2);
        float4 q3 = __ldg(rowp + 3);
        float v[16] = { q0.x, q0.y, q0.z, q0.w,
                        q1.x, q1.y, q1.z, q1.w,
                        q2.x, q2.y, q2.z, q2.w,
                        q3.x, q3.y, q3.z, q3.w };

        if (w) {
            // ---- Batcher odd-even merge sort, 16 elems, descending (63 CEs) ----
            CE(0,1)  CE(2,3)  CE(4,5)  CE(6,7)  CE(8,9)  CE(10,11) CE(12,13) CE(14,15)
            CE(0,2)  CE(1,3)  CE(4,6)  CE(5,7)  CE(8,10) CE(9,11)  CE(12,14) CE(13,15)
            CE(1,2)  CE(5,6)  CE(9,10) CE(13,14)
            CE(0,4)  CE(1,5)  CE(2,6)  CE(3,7)  CE(8,12) CE(9,13)  CE(10,14) CE(11,15)
            CE(2,4)  CE(3,5)  CE(10,12) CE(11,13)
            CE(1,2)  CE(3,4)  CE(5,6)  CE(9,10) CE(11,12) CE(13,14)
            CE(0,8)  CE(1,9)  CE(2,10) CE(3,11) CE(4,12) CE(5,13)  CE(6,14)  CE(7,15)
            CE(4,8)  CE(5,9)  CE(6,10) CE(7,11)
            CE(2,4)  CE(3,5)  CE(6,8)  CE(7,9)  CE(10,12) CE(11,13)
            CE(1,2)  CE(3,4)  CE(5,6)  CE(7,8)  CE(9,10)  CE(11,12) CE(13,14)

            const float m    = v[0];                 // sorted => max is v[0]
            const float mL2E = m * L2E_;
            float dot = 0.0f, Z = 0.0f;
#pragma unroll
            for (int r = 0; r < 16; r++) {
                float ex = ex2f(fmaf(v[r], L2E_, -mL2E));
                dot = fmaf(ex, v[r], dot);           // sum e_i * x_i
                Z  += ex;
                v[r] = ex;                           // overwrite logits with exps (sorted desc)
            }
            const float rcpZ = __fdividef(1.0f, Z);
            const float H = __logf(Z) + m - rcpZ * dot - 16.0f * EPSF_;
            entS += H;

            // kept(rank r) <=> prefix-before-r <= thr ; broadcast keeps all
            const float thr = (H >= BCT_) ? __int_as_float(0x7f800000) : TOPP_ * Z;
            float cp = 0.0f;
#pragma unroll
            for (int r = 0; r < 16; r++) {
                if (cp <= thr) {
                    A[r] += 1.0f;
                    P[r] = fmaf(v[r], rcpZ, P[r]);
                }
                cp += v[r];
            }
        } else {
            // entropy-only path (no sort needed)
            float m01 = fmaxf(v[0], v[1]),   m23 = fmaxf(v[2], v[3]);
            float m45 = fmaxf(v[4], v[5]),   m67 = fmaxf(v[6], v[7]);
            float m89 = fmaxf(v[8], v[9]),   mab = fmaxf(v[10], v[11]);
            float mcd = fmaxf(v[12], v[13]), mef = fmaxf(v[14], v[15]);
            float ma = fmaxf(fmaxf(m01, m23), fmaxf(m45, m67));
            float mb = fmaxf(fmaxf(m89, mab), fmaxf(mcd, mef));
            const float m    = fmaxf(ma, mb);
            const float mL2E = m * L2E_;
            float dot = 0.0f, Z = 0.0f;
#pragma unroll
            for (int r = 0; r < 16; r++) {
                float ex = ex2f(fmaf(v[r], L2E_, -mL2E));
                dot = fmaf(ex, v[r], dot);
                Z  += ex;
            }
            entS += __logf(Z) + m - __fdividef(dot, Z) - 16.0f * EPSF_;
        }
    }

    // ---- warp butterfly reduction of 33 accumulators, one atomic set per warp ----
#pragma unroll
    for (int r = 0; r < 16; r++) {
#pragma unroll
        for (int s = 16; s > 0; s >>= 1) {
            A[r] += __shfl_xor_sync(0xffffffffu, A[r], s);
            P[r] += __shfl_xor_sync(0xffffffffu, P[r], s);
        }
    }
#pragma unroll
    for (int s = 16; s > 0; s >>= 1) entS += __shfl_xor_sync(0xffffffffu, entS, s);

    if (lane == 0) {
#pragma unroll
        for (int r = 0; r < 16; r++) {
            atomicAdd(&g_acc[r],      A[r]);
            atomicAdd(&g_acc[16 + r], P[r]);
        }
        atomicAdd(&g_acc[32], entS);
    }
}

__global__ void dynmole_final(const int* __restrict__ attn, float* __restrict__ out) {
    __shared__ float red[256];
    float s = 0.0f;
    for (int i = threadIdx.x; i < BS_; i += 256) s += (float)__ldg(attn + i);
    red[threadIdx.x] = s;
    __syncthreads();
    for (int off = 128; off > 0; off >>= 1) {
        if (threadIdx.x < off) red[threadIdx.x] += red[threadIdx.x + off];
        __syncthreads();
    }
    if (threadIdx.x == 0) {
        const float denom = (float)L_ * red[0];
        const float inv   = 1.0f / denom;
        float overall = 0.0f;
#pragma unroll
        for (int r = 0; r < 16; r++) overall += g_acc[r] * g_acc[16 + r];
        overall *= inv * inv;
        const float ent = g_acc[32] * (1.0f / NROWSF);
        out[0] = ent * DYN_ + overall * (float)E_ * AUX_;
    }
}

extern "C" void kernel_launch(void* const* d_in, const int* in_sizes, int n_in,
                              void* d_out, int out_size) {
    const float* logits;
    const int*   attn;
    // defensive input-order resolution by element count
    if (in_sizes[0] == L_ * BS_ * E_) {
        logits = (const float*)d_in[0];
        attn   = (const int*)d_in[1];
    } else {
        logits = (const float*)d_in[1];
        attn   = (const int*)d_in[0];
    }
    float* out = (float*)d_out;

    dynmole_init<<<1, 64>>>();
    dynmole_main<<<296, 256>>>(logits, attn);
    dynmole_final<<<1, 256>>>(attn, out);
}

// round 2
// speedup vs baseline: 3.7448x; 3.7448x over previous
#include <cuda_runtime.h>
#include <cstddef>

// DynMoleRouterLoss fused single-kernel version.
// Mapping: warp <-> (layer l, token-block tb of 32 tokens); lane <-> token within block.
// Loads are fully coalesced (2KB contiguous per warp per iteration).
// attn weight w varies per lane; sort runs for all warps, w only gates A/P accumulation.

namespace {
constexpr int   L_     = 32;
constexpr int   BS_    = 8 * 4096;          // 32768 tokens
constexpr int   E_     = 16;
constexpr int   TPB    = 256;
constexpr int   NB     = 296;               // 2 blocks/SM on 148 SMs, exactly 1 wave
constexpr int   WPB    = TPB / 32;
constexpr int   NW     = NB * WPB;          // 2368 warps
constexpr int   UNITS  = L_ * (BS_ / 32);   // 32768 warp-units
constexpr float TOPP_  = 0.8f;
constexpr float EPSF_  = 1e-5f;
constexpr float BCT_   = 2.0f;
constexpr float L2E_   = 1.4426950408889634f;
constexpr float DYN_   = 0.001f;
constexpr float AUX_   = 0.001f;
constexpr float NROWSF = 1048576.0f;        // L*BS
}

// per-block partials: [0..15]=A, [16..31]=P, [32]=entropy, [33]=sum of w (== L*sum(attn))
__device__ float    g_part[NB][34];
__device__ unsigned g_ctr = 0;

__device__ __forceinline__ float ex2f(float x) {
    float y;
    asm("ex2.approx.ftz.f32 %0, %1;" : "=f"(y) : "f"(x));
    return y;
}

// compare-exchange, DESCENDING: v[i] >= v[j] afterwards
#define CE(i, j) { float _a = v[i], _b = v[j]; v[i] = fmaxf(_a, _b); v[j] = fminf(_a, _b); }

__global__ __launch_bounds__(TPB, 2) void dynmole_fused(
        const float* __restrict__ logits, const int* __restrict__ attn,
        float* __restrict__ out) {
    const int lane = threadIdx.x & 31;
    const int warp = threadIdx.x >> 5;
    const int wg   = blockIdx.x * WPB + warp;

    float    P[16];
    unsigned A2[8];
#pragma unroll
    for (int r = 0; r < 16; r++) P[r] = 0.0f;
#pragma unroll
    for (int i = 0; i < 8;  i++) A2[i] = 0u;
    float entS = 0.0f, wS = 0.0f;

    // ---------------- software-pipelined main loop ----------------
    int u = wg;
    float4 q0, q1, q2, q3;
    int    w = 0;
    if (u < UNITS) {
        const int l = u >> 10, tbi = u & 1023;
        const float4* p = reinterpret_cast<const float4*>(logits)
                        + ((size_t)(l * BS_ + tbi * 32 + lane) << 2);
        q0 = __ldg(p + 0); q1 = __ldg(p + 1); q2 = __ldg(p + 2); q3 = __ldg(p + 3);
        w  = __ldg(attn + tbi * 32 + lane);
    }

    while (u < UNITS) {
        float v[16] = { q0.x, q0.y, q0.z, q0.w,  q1.x, q1.y, q1.z, q1.w,
                        q2.x, q2.y, q2.z, q2.w,  q3.x, q3.y, q3.z, q3.w };
        const int curw = w;

        // prefetch next iteration (hides DRAM latency behind the compute chain)
        const int un = u + NW;
        if (un < UNITS) {
            const int l = un >> 10, tbi = un & 1023;
            const float4* p = reinterpret_cast<const float4*>(logits)
                            + ((size_t)(l * BS_ + tbi * 32 + lane) << 2);
            q0 = __ldg(p + 0); q1 = __ldg(p + 1); q2 = __ldg(p + 2); q3 = __ldg(p + 3);
            w  = __ldg(attn + tbi * 32 + lane);
        }
        u = un;

        // ---- Batcher odd-even merge sort, 16 elems, descending (63 CEs) ----
        CE(0,1)  CE(2,3)  CE(4,5)  CE(6,7)  CE(8,9)  CE(10,11) CE(12,13) CE(14,15)
        CE(0,2)  CE(1,3)  CE(4,6)  CE(5,7)  CE(8,10) CE(9,11)  CE(12,14) CE(13,15)
        CE(1,2)  CE(5,6)  CE(9,10) CE(13,14)
        CE(0,4)  CE(1,5)  CE(2,6)  CE(3,7)  CE(8,12) CE(9,13)  CE(10,14) CE(11,15)
        CE(2,4)  CE(3,5)  CE(10,12) CE(11,13)
        CE(1,2)  CE(3,4)  CE(5,6)  CE(9,10) CE(11,12) CE(13,14)
        CE(0,8)  CE(1,9)  CE(2,10) CE(3,11) CE(4,12) CE(5,13)  CE(6,14)  CE(7,15)
        CE(4,8)  CE(5,9)  CE(6,10) CE(7,11)
        CE(2,4)  CE(3,5)  CE(6,8)  CE(7,9)  CE(10,12) CE(11,13)
        CE(1,2)  CE(3,4)  CE(5,6)  CE(7,8)  CE(9,10)  CE(11,12) CE(13,14)

        // ---- softmax stats from sorted logits (max = v[0]) ----
        const float m    = v[0];
        const float mL2E = m * L2E_;
        float dot = 0.0f, Z = 0.0f;
#pragma unroll
        for (int r = 0; r < 16; r++) {
            float ex = ex2f(fmaf(v[r], L2E_, -mL2E));
            dot = fmaf(ex, v[r], dot);          // sum e_i * x_i
            Z  += ex;
            v[r] = ex;                           // sorted descending exps
        }
        const float rcpZ = __fdividef(1.0f, Z);
        const float H = __logf(Z) + m - rcpZ * dot - 16.0f * EPSF_;
        entS += H;
        wS   += (float)curw;

        // kept(rank r) <=> prefix-before-r <= thr
        // w==0: thr=-1 (nothing kept); broadcast: thr=+inf (all kept)
        const float thr = curw ? ((H >= BCT_) ? __int_as_float(0x7f800000) : TOPP_ * Z)
                               : -1.0f;
        float cp = 0.0f;
#pragma unroll
        for (int i = 0; i < 8; i++) {
            unsigned inc = 0u;
            if (cp <= thr) { P[2*i]   = fmaf(v[2*i],   rcpZ, P[2*i]);   inc  = 1u; }
            cp += v[2*i];
            if (cp <= thr) { P[2*i+1] = fmaf(v[2*i+1], rcpZ, P[2*i+1]); inc |= 0x10000u; }
            cp += v[2*i+1];
            A2[i] += inc;
        }
    }

    // ---------------- warp butterfly reduction ----------------
#pragma unroll
    for (int r = 0; r < 16; r++)
#pragma unroll
        for (int s = 16; s > 0; s >>= 1)
            P[r] += __shfl_xor_sync(0xffffffffu, P[r], s);
#pragma unroll
    for (int i = 0; i < 8; i++)
#pragma unroll
        for (int s = 16; s > 0; s >>= 1)
            A2[i] += __shfl_xor_sync(0xffffffffu, A2[i], s);   // halves can't overflow (<=448)
#pragma unroll
    for (int s = 16; s > 0; s >>= 1) {
        entS += __shfl_xor_sync(0xffffffffu, entS, s);
        wS   += __shfl_xor_sync(0xffffffffu, wS,   s);
    }

    // ---------------- block reduction into shared ----------------
    __shared__ float sacc[34];
    if (threadIdx.x < 34) sacc[threadIdx.x] = 0.0f;
    __syncthreads();
    if (lane == 0) {
#pragma unroll
        for (int i = 0; i < 8; i++) {
            atomicAdd(&sacc[2*i],     (float)(A2[i] & 0xFFFFu));
            atomicAdd(&sacc[2*i + 1], (float)(A2[i] >> 16));
        }
#pragma unroll
        for (int r = 0; r < 16; r++) atomicAdd(&sacc[16 + r], P[r]);
        atomicAdd(&sacc[32], entS);
        atomicAdd(&sacc[33], wS);
    }
    __syncthreads();
    if (threadIdx.x < 34) g_part[blockIdx.x][threadIdx.x] = sacc[threadIdx.x];
    __threadfence();
    __syncthreads();

    // ---------------- last block folds everything ----------------
    __shared__ bool s_last;
    if (threadIdx.x == 0) {
        unsigned old = atomicAdd(&g_ctr, 1u);
        s_last = (old == (unsigned)(NB - 1));
    }
    __syncthreads();
    if (!s_last) return;

    if (threadIdx.x < 34) sacc[threadIdx.x] = 0.0f;
    __syncthreads();
    {   // 7 groups x 34 values; group g sums blocks g, g+7, g+14, ...
        const int t = threadIdx.x;
        if (t < 238) {
            const int v = t % 34, g = t / 34;
            float s = 0.0f;
            for (int b = g; b < NB; b += 7) s += g_part[b][v];
            atomicAdd(&sacc[v], s);
        }
    }
    __syncthreads();
    if (threadIdx.x == 0) {
        const float denom = sacc[33];            // == L * sum(attn)
        const float inv   = 1.0f / denom;
        float overall = 0.0f;
#pragma unroll
        for (int r = 0; r < 16; r++) overall += sacc[r] * sacc[16 + r];
        overall *= inv * inv;
        out[0] = (sacc[32] * (1.0f / NROWSF)) * DYN_ + overall * (float)E_ * AUX_;
        g_ctr = 0;                                // reset for next graph replay
    }
}

extern "C" void kernel_launch(void* const* d_in, const int* in_sizes, int n_in,
                              void* d_out, int out_size) {
    const float* logits;
    const int*   attn;
    if (in_sizes[0] == L_ * BS_ * E_) {
        logits = (const float*)d_in[0];
        attn   = (const int*)d_in[1];
    } else {
        logits = (const float*)d_in[1];
        attn   = (const int*)d_in[0];
    }
    dynmole_fused<<<NB, TPB>>>(logits, attn, (float*)d_out);
}

// round 3
// speedup vs baseline: 4.1065x; 1.0966x over previous
#include <cuda_runtime.h>
#include <cstddef>

// DynMoleRouterLoss fused single-kernel, round 3.
// warp <-> 32 consecutive rows (row = u*32 + lane); fully coalesced 2KB/warp/iter.
// Prefix-before stored in-place => compare loop has no serial chain.
// Block partials RED-added into g_acc; last block (g_ctr) finalizes.

namespace {
constexpr int   L_     = 32;
constexpr int   BS_    = 8 * 4096;          // 32768 tokens
constexpr int   E_     = 16;
constexpr int   TPB    = 256;
constexpr int   NB     = 296;               // 2 blocks/SM, one wave
constexpr int   WPB    = TPB / 32;
constexpr int   NW     = NB * WPB;          // 2368 warps
constexpr int   UNITS  = 32768;             // warp-units (L*BS/32)
constexpr float TOPP_  = 0.8f;
constexpr float EPSF_  = 1e-5f;
constexpr float BCT_   = 2.0f;
constexpr float L2E_   = 1.4426950408889634f;
constexpr float DYN_   = 0.001f;
constexpr float AUX_   = 0.001f;
constexpr float NROWSF = 1048576.0f;        // L*BS
}

// [0..15]=A counts per rank, [16..31]=P sums per rank, [32]=entropy, [33]=sum w
__device__ float    g_acc[34];
__device__ unsigned g_ctr = 0;

__device__ __forceinline__ float ex2f(float x) {
    float y;
    asm("ex2.approx.ftz.f32 %0, %1;" : "=f"(y) : "f"(x));
    return y;
}

// compare-exchange, DESCENDING: v[i] >= v[j] afterwards
#define CE(i, j) { float _a = v[i], _b = v[j]; v[i] = fmaxf(_a, _b); v[j] = fminf(_a, _b); }

__global__ __launch_bounds__(TPB, 2) void dynmole_fused(
        const float* __restrict__ logits, const int* __restrict__ attn,
        float* __restrict__ out) {
    const int lane = threadIdx.x & 31;
    const int warp = threadIdx.x >> 5;
    const int wg   = blockIdx.x * WPB + warp;

    float    P[16];
    unsigned A2[8];
#pragma unroll
    for (int r = 0; r < 16; r++) P[r] = 0.0f;
#pragma unroll
    for (int i = 0; i < 8;  i++) A2[i] = 0u;
    float    entS = 0.0f;
    unsigned wSum = 0u;

    // ---------------- software-pipelined main loop ----------------
    int u = wg;
    float4 q0, q1, q2, q3;
    int    w = 0;
    if (u < UNITS) {
        const float4* p = reinterpret_cast<const float4*>(logits)
                        + ((size_t)(u * 32 + lane) << 2);
        q0 = __ldg(p + 0); q1 = __ldg(p + 1); q2 = __ldg(p + 2); q3 = __ldg(p + 3);
        w  = __ldg(attn + ((u & 1023) * 32 + lane));
    }

    while (u < UNITS) {
        float v[16] = { q0.x, q0.y, q0.z, q0.w,  q1.x, q1.y, q1.z, q1.w,
                        q2.x, q2.y, q2.z, q2.w,  q3.x, q3.y, q3.z, q3.w };
        const int curw = w;

        const int un = u + NW;
        if (un < UNITS) {   // prefetch next iteration
            const float4* p = reinterpret_cast<const float4*>(logits)
                            + ((size_t)(un * 32 + lane) << 2);
            q0 = __ldg(p + 0); q1 = __ldg(p + 1); q2 = __ldg(p + 2); q3 = __ldg(p + 3);
            w  = __ldg(attn + ((un & 1023) * 32 + lane));
        }
        u = un;

        // ---- Batcher odd-even merge sort, 16 elems, descending (63 CEs) ----
        CE(0,1)  CE(2,3)  CE(4,5)  CE(6,7)  CE(8,9)  CE(10,11) CE(12,13) CE(14,15)
        CE(0,2)  CE(1,3)  CE(4,6)  CE(5,7)  CE(8,10) CE(9,11)  CE(12,14) CE(13,15)
        CE(1,2)  CE(5,6)  CE(9,10) CE(13,14)
        CE(0,4)  CE(1,5)  CE(2,6)  CE(3,7)  CE(8,12) CE(9,13)  CE(10,14) CE(11,15)
        CE(2,4)  CE(3,5)  CE(10,12) CE(11,13)
        CE(1,2)  CE(3,4)  CE(5,6)  CE(9,10) CE(11,12) CE(13,14)
        CE(0,8)  CE(1,9)  CE(2,10) CE(3,11) CE(4,12) CE(5,13)  CE(6,14)  CE(7,15)
        CE(4,8)  CE(5,9)  CE(6,10) CE(7,11)
        CE(2,4)  CE(3,5)  CE(6,8)  CE(7,9)  CE(10,12) CE(11,13)
        CE(1,2)  CE(3,4)  CE(5,6)  CE(7,8)  CE(9,10)  CE(11,12) CE(13,14)

        // ---- exp + dot + in-place prefix-before (v[r] <- sum_{j<r} exp_j) ----
        const float m    = v[0];
        const float mL2E = m * L2E_;
        float dot = 0.0f, cp = 0.0f;
#pragma unroll
        for (int r = 0; r < 16; r++) {
            const float ex = ex2f(fmaf(v[r], L2E_, -mL2E));
            dot = fmaf(ex, v[r], dot);
            const float nxt = cp + ex;
            v[r] = cp;                        // prefix BEFORE rank r
            cp = nxt;
        }
        const float Z    = cp;
        const float rcpZ = __fdividef(1.0f, Z);
        const float H    = __logf(Z) + m - dot * rcpZ - 16.0f * EPSF_;
        entS += H;
        wSum += (unsigned)curw;

        // kept(r) <=> pb[r] <= 0.8*Z (or broadcast); w==0 keeps nothing
        const float thrZ = curw ? TOPP_ * Z : -1.0f;
        const bool  bc   = curw && (H >= BCT_);
#pragma unroll
        for (int i = 0; i < 8; i++) {
            const int r0 = 2 * i, r1 = 2 * i + 1;
            const bool k0 = (v[r0] <= thrZ) | bc;
            const bool k1 = (v[r1] <= thrZ) | bc;
            const float n1 = (r1 == 15) ? Z : v[r1 + 1];
            if (k0) P[r0] = fmaf(v[r1] - v[r0], rcpZ, P[r0]);
            if (k1) P[r1] = fmaf(n1    - v[r1], rcpZ, P[r1]);
            if (k0) A2[i] += 1u;
            if (k1) A2[i] += 0x10000u;
        }
    }

    // ---------------- warp butterfly reduction ----------------
#pragma unroll
    for (int r = 0; r < 16; r++)
#pragma unroll
        for (int s = 16; s > 0; s >>= 1)
            P[r] += __shfl_xor_sync(0xffffffffu, P[r], s);
#pragma unroll
    for (int i = 0; i < 8; i++)
#pragma unroll
        for (int s = 16; s > 0; s >>= 1)
            A2[i] += __shfl_xor_sync(0xffffffffu, A2[i], s);   // halves <= 448, no overflow
    float wS = (float)wSum;
#pragma unroll
    for (int s = 16; s > 0; s >>= 1) {
        entS += __shfl_xor_sync(0xffffffffu, entS, s);
        wS   += __shfl_xor_sync(0xffffffffu, wS,   s);
    }

    // ---------------- block reduce (smem) then RED into g_acc ----------------
    __shared__ float sred[WPB][34];
    if (lane == 0) {
#pragma unroll
        for (int i = 0; i < 8; i++) {
            sred[warp][2*i]     = (float)(A2[i] & 0xFFFFu);
            sred[warp][2*i + 1] = (float)(A2[i] >> 16);
        }
#pragma unroll
        for (int r = 0; r < 16; r++) sred[warp][16 + r] = P[r];
        sred[warp][32] = entS;
        sred[warp][33] = wS;
    }
    __syncthreads();
    if (threadIdx.x < 34) {
        float s = 0.0f;
#pragma unroll
        for (int j = 0; j < WPB; j++) s += sred[j][threadIdx.x];
        atomicAdd(&g_acc[threadIdx.x], s);     // no return use -> RED
        __threadfence();
    }
    __syncthreads();

    // ---------------- last block finalizes ----------------
    __shared__ bool  s_last;
    __shared__ float sacc[34];
    if (threadIdx.x == 0) {
        unsigned old = atomicAdd(&g_ctr, 1u);
        s_last = (old == (unsigned)(NB - 1));
    }
    __syncthreads();
    if (!s_last) return;

    __threadfence();                           // acquire: all g_acc REDs visible
    if (threadIdx.x < 34) {
        sacc[threadIdx.x] = atomicAdd(&g_acc[threadIdx.x], 0.0f);  // coherent read
    }
    __syncthreads();
    if (threadIdx.x == 0) {
        const float denom = sacc[33];          // == L * sum(attn)
        const float inv   = 1.0f / denom;
        float overall = 0.0f;
#pragma unroll
        for (int r = 0; r < 16; r++) overall += sacc[r] * sacc[16 + r];
        overall *= inv * inv;
        out[0] = (sacc[32] * (1.0f / NROWSF)) * DYN_ + overall * (float)E_ * AUX_;
        g_ctr = 0;                             // reset for next replay
    }
    if (threadIdx.x < 34) g_acc[threadIdx.x] = 0.0f;
}

extern "C" void kernel_launch(void* const* d_in, const int* in_sizes, int n_in,
                              void* d_out, int out_size) {
    const float* logits;
    const int*   attn;
    if (in_sizes[0] == L_ * BS_ * E_) {
        logits = (const float*)d_in[0];
        attn   = (const int*)d_in[1];
    } else {
        logits = (const float*)d_in[1];
        attn   = (const int*)d_in[0];
    }
    dynmole_fused<<<NB, TPB>>>(logits, attn, (float*)d_out);
}

// round 7
// speedup vs baseline: 4.7239x; 1.1503x over previous
#include <cuda_runtime.h>
#include <cuda_fp16.h>
#include <cstddef>

// DynMoleRouterLoss fused: paired-row f16x2 sorting network.
// (3rd submission — rounds 4/5 died to GB300 container acquisition, same infra
//  error as round 0's empty stub; kernel has never executed.)
// Thread processes rows (lp*BS + t) and ((lp+16)*BS + t)  [same token => same attn w].
// Keys packed half2{A,B}; one 63-CE Batcher network sorts both rows at once.
// All math after the sort is fp32, self-consistent with the fp16-rounded keys.

namespace {
constexpr int   L_     = 32;
constexpr int   BS_    = 8 * 4096;          // 32768 tokens
constexpr int   E_     = 16;
constexpr int   TPB    = 256;
constexpr int   NB     = 296;               // 2 blocks/SM, one wave
constexpr int   WPB    = TPB / 32;
constexpr int   NW     = NB * WPB;          // 2368 warps
constexpr int   UNITSP = 16384;             // pair-units: (L/2) * BS / 32
constexpr int   ROWOFF = 16 * BS_;          // row distance between pair members
constexpr float TOPP_  = 0.8f;
constexpr float EPSF_  = 1e-5f;
constexpr float BCT_   = 2.0f;
constexpr float L2E_   = 1.4426950408889634f;
constexpr float LN2_   = 0.6931471805599453f;
constexpr float DYN_   = 0.001f;
constexpr float AUX_   = 0.001f;
constexpr float NROWSF = 1048576.0f;        // L*BS
}

// [0..15]=A counts, [16..31]=P sums, [32]=entropy, [33]=sum w (pair-units)
__device__ float    g_acc[34];
__device__ unsigned g_ctr = 0;

__device__ __forceinline__ float ex2f(float x) {
    float y; asm("ex2.approx.ftz.f32 %0, %1;" : "=f"(y) : "f"(x)); return y;
}
__device__ __forceinline__ float lg2f(float x) {
    float y; asm("lg2.approx.ftz.f32 %0, %1;" : "=f"(y) : "f"(x)); return y;
}
__device__ __forceinline__ float rcpf(float x) {
    float y; asm("rcp.approx.ftz.f32 %0, %1;" : "=f"(y) : "f"(x)); return y;
}

// packed compare-exchange, DESCENDING per half: h[i] >= h[j] elementwise after
#define CE(i, j) { __half2 _a = h[i], _b = h[j]; h[i] = __hmax2(_a, _b); h[j] = __hmin2(_a, _b); }

// process one row given sorted fp16 keys (GETF extracts half -> float)
#define PROCESS_ROW(GETF)                                                        \
    {                                                                            \
        float pb[16];                                                            \
        const float m    = GETF(h[0]);                                           \
        const float mL2E = m * L2E_;                                             \
        float dot = 0.0f, cp = 0.0f;                                             \
        _Pragma("unroll")                                                        \
        for (int r = 0; r < 16; r++) {                                           \
            const float x  = GETF(h[r]);                                         \
            const float ex = ex2f(fmaf(x, L2E_, -mL2E));                         \
            dot = fmaf(ex, x, dot);                                              \
            pb[r] = cp;                                                          \
            cp += ex;                                                            \
        }                                                                        \
        const float Z    = cp;                                                   \
        const float rcpZ = rcpf(Z);                                              \
        const float H    = lg2f(Z) * LN2_ + m - dot * rcpZ - 16.0f * EPSF_;      \
        entS += H;                                                               \
        const float thr = curw ? ((H >= BCT_) ? __int_as_float(0x7f800000)       \
                                              : TOPP_ * Z)                       \
                               : -1.0f;                                          \
        _Pragma("unroll")                                                        \
        for (int r = 0; r < 16; r++) {                                           \
            const bool  k  = (pb[r] <= thr);                                     \
            const float nx = (r == 15) ? Z : pb[r + 1];                          \
            if (k) P[r] = fmaf(nx - pb[r], rcpZ, P[r]);                          \
            if (k) A8[r >> 2] += (1u << ((r & 3) * 8));                          \
        }                                                                        \
    }

__global__ __launch_bounds__(TPB, 2) void dynmole_fused(
        const float* __restrict__ logits, const int* __restrict__ attn,
        float* __restrict__ out) {
    const int lane = threadIdx.x & 31;
    const int warp = threadIdx.x >> 5;
    const int wg   = blockIdx.x * WPB + warp;

    float    P[16];
    unsigned A8[4];                       // 16 byte counters (max 2*7=14 each)
#pragma unroll
    for (int r = 0; r < 16; r++) P[r] = 0.0f;
#pragma unroll
    for (int i = 0; i < 4;  i++) A8[i] = 0u;
    float entS = 0.0f, wS = 0.0f;

    // ---------------- software-pipelined main loop ----------------
    int pu = wg;
    float4 a0, a1, a2, a3, b0, b1, b2, b3;
    int    w = 0;
    if (pu < UNITSP) {
        const int rowA = pu * 32 + lane;
        const float4* pa = reinterpret_cast<const float4*>(logits) + ((size_t)rowA << 2);
        const float4* pb_ = pa + ((size_t)ROWOFF << 2);
        a0 = __ldg(pa + 0); a1 = __ldg(pa + 1); a2 = __ldg(pa + 2); a3 = __ldg(pa + 3);
        b0 = __ldg(pb_ + 0); b1 = __ldg(pb_ + 1); b2 = __ldg(pb_ + 2); b3 = __ldg(pb_ + 3);
        w  = __ldg(attn + (rowA & (BS_ - 1)));
    }

    while (pu < UNITSP) {
        // pack keys: half2{rowA (low), rowB (high)}
        __half2 h[16];
        h[ 0]=__floats2half2_rn(a0.x,b0.x); h[ 1]=__floats2half2_rn(a0.y,b0.y);
        h[ 2]=__floats2half2_rn(a0.z,b0.z); h[ 3]=__floats2half2_rn(a0.w,b0.w);
        h[ 4]=__floats2half2_rn(a1.x,b1.x); h[ 5]=__floats2half2_rn(a1.y,b1.y);
        h[ 6]=__floats2half2_rn(a1.z,b1.z); h[ 7]=__floats2half2_rn(a1.w,b1.w);
        h[ 8]=__floats2half2_rn(a2.x,b2.x); h[ 9]=__floats2half2_rn(a2.y,b2.y);
        h[10]=__floats2half2_rn(a2.z,b2.z); h[11]=__floats2half2_rn(a2.w,b2.w);
        h[12]=__floats2half2_rn(a3.x,b3.x); h[13]=__floats2half2_rn(a3.y,b3.y);
        h[14]=__floats2half2_rn(a3.z,b3.z); h[15]=__floats2half2_rn(a3.w,b3.w);
        const int curw = w;

        const int un = pu + NW;
        if (un < UNITSP) {     // prefetch next pair (8x LDG.128 + attn)
            const int rowA = un * 32 + lane;
            const float4* pa = reinterpret_cast<const float4*>(logits) + ((size_t)rowA << 2);
            const float4* pb_ = pa + ((size_t)ROWOFF << 2);
            a0 = __ldg(pa + 0); a1 = __ldg(pa + 1); a2 = __ldg(pa + 2); a3 = __ldg(pa + 3);
            b0 = __ldg(pb_ + 0); b1 = __ldg(pb_ + 1); b2 = __ldg(pb_ + 2); b3 = __ldg(pb_ + 3);
            w  = __ldg(attn + (rowA & (BS_ - 1)));
        }
        pu = un;

        // ---- dual Batcher odd-even merge sort, descending (63 packed CEs) ----
        CE(0,1)  CE(2,3)  CE(4,5)  CE(6,7)  CE(8,9)  CE(10,11) CE(12,13) CE(14,15)
        CE(0,2)  CE(1,3)  CE(4,6)  CE(5,7)  CE(8,10) CE(9,11)  CE(12,14) CE(13,15)
        CE(1,2)  CE(5,6)  CE(9,10) CE(13,14)
        CE(0,4)  CE(1,5)  CE(2,6)  CE(3,7)  CE(8,12) CE(9,13)  CE(10,14) CE(11,15)
        CE(2,4)  CE(3,5)  CE(10,12) CE(11,13)
        CE(1,2)  CE(3,4)  CE(5,6)  CE(9,10) CE(11,12) CE(13,14)
        CE(0,8)  CE(1,9)  CE(2,10) CE(3,11) CE(4,12) CE(5,13)  CE(6,14)  CE(7,15)
        CE(4,8)  CE(5,9)  CE(6,10) CE(7,11)
        CE(2,4)  CE(3,5)  CE(6,8)  CE(7,9)  CE(10,12) CE(11,13)
        CE(1,2)  CE(3,4)  CE(5,6)  CE(7,8)  CE(9,10)  CE(11,12) CE(13,14)

        wS += (float)curw;
        PROCESS_ROW(__low2float)      // row A
        PROCESS_ROW(__high2float)     // row B
    }

    // ---------------- expand byte counters to 16-bit pairs ----------------
    unsigned A16[8];
#pragma unroll
    for (int i = 0; i < 4; i++) {
        A16[2*i]     = A8[i] & 0x00FF00FFu;          // ranks 4i, 4i+2
        A16[2*i + 1] = (A8[i] >> 8) & 0x00FF00FFu;   // ranks 4i+1, 4i+3
    }

    // ---------------- warp butterfly reduction ----------------
#pragma unroll
    for (int r = 0; r < 16; r++)
#pragma unroll
        for (int s = 16; s > 0; s >>= 1)
            P[r] += __shfl_xor_sync(0xffffffffu, P[r], s);
#pragma unroll
    for (int i = 0; i < 8; i++)
#pragma unroll
        for (int s = 16; s > 0; s >>= 1)
            A16[i] += __shfl_xor_sync(0xffffffffu, A16[i], s);   // fields <= 448
#pragma unroll
    for (int s = 16; s > 0; s >>= 1) {
        entS += __shfl_xor_sync(0xffffffffu, entS, s);
        wS   += __shfl_xor_sync(0xffffffffu, wS,   s);
    }

    // ---------------- block reduce (smem) then RED into g_acc ----------------
    __shared__ float sred[WPB][34];
    if (lane == 0) {
#pragma unroll
        for (int i = 0; i < 4; i++) {
            sred[warp][4*i + 0] = (float)(A16[2*i]     & 0xFFFFu);
            sred[warp][4*i + 2] = (float)(A16[2*i]     >> 16);
            sred[warp][4*i + 1] = (float)(A16[2*i + 1] & 0xFFFFu);
            sred[warp][4*i + 3] = (float)(A16[2*i + 1] >> 16);
        }
#pragma unroll
        for (int r = 0; r < 16; r++) sred[warp][16 + r] = P[r];
        sred[warp][32] = entS;
        sred[warp][33] = wS;
    }
    __syncthreads();
    if (threadIdx.x < 34) {
        float s = 0.0f;
#pragma unroll
        for (int j = 0; j < WPB; j++) s += sred[j][threadIdx.x];
        atomicAdd(&g_acc[threadIdx.x], s);
        __threadfence();
    }
    __syncthreads();

    // ---------------- last block finalizes ----------------
    __shared__ bool  s_last;
    __shared__ float sacc[34];
    if (threadIdx.x == 0) {
        unsigned old = atomicAdd(&g_ctr, 1u);
        s_last = (old == (unsigned)(NB - 1));
    }
    __syncthreads();
    if (!s_last) return;

    __threadfence();
    if (threadIdx.x < 34)
        sacc[threadIdx.x] = atomicAdd(&g_acc[threadIdx.x], 0.0f);
    __syncthreads();
    if (threadIdx.x == 0) {
        const float denom = 2.0f * sacc[33];     // == L * sum(attn)
        const float inv   = 1.0f / denom;
        float overall = 0.0f;
#pragma unroll
        for (int r = 0; r < 16; r++) overall += sacc[r] * sacc[16 + r];
        overall *= inv * inv;
        out[0] = (sacc[32] * (1.0f / NROWSF)) * DYN_ + overall * (float)E_ * AUX_;
        g_ctr = 0;                               // reset for next replay
    }
    if (threadIdx.x < 34) g_acc[threadIdx.x] = 0.0f;
}

extern "C" void kernel_launch(void* const* d_in, const int* in_sizes, int n_in,
                              void* d_out, int out_size) {
    const float* logits;
    const int*   attn;
    if (in_sizes[0] == L_ * BS_ * E_) {
        logits = (const float*)d_in[0];
        attn   = (const int*)d_in[1];
    } else {
        logits = (const float*)d_in[1];
        attn   = (const int*)d_in[0];
    }
    dynmole_fused<<<NB, TPB>>>(logits, attn, (float*)d_out);
}